// round 7
// baseline (speedup 1.0000x reference)
#include <cuda_runtime.h>
#include <cstdint>

// ---------------- problem shape ----------------
#define BATCH 32
#define CIN   64
#define HIN   128
#define WIN   128
#define COUT  128
#define HO    126
#define WO    126
#define NGRP  8
#define HP    63
#define WP    63
#define EPS   1e-5f

#define CI_STRIDE 552                 // words per ci: 4 rows * 136 + 8 pad (conflict-free)
#define XS_ELEMS  (16 * CI_STRIDE)    // 8832 words per buffer

// ---------------- scratch (static device globals) ----------------
__device__ float g_pmax[(size_t)BATCH * COUT * HP * WP];
__device__ float g_pmin[(size_t)BATCH * COUT * HP * WP];
__device__ float g_wA[72 * 8 * 32 * 4];
__device__ float g_sum[BATCH * NGRP];
__device__ float g_sumsq[BATCH * NGRP];
__device__ float g_mean[BATCH * NGRP];
__device__ float g_rstd[BATCH * NGRP];

static __device__ __forceinline__ uint32_t f2tf32(float v) {
    uint32_t t;
    asm("cvt.rna.tf32.f32 %0, %1;" : "=r"(t) : "f"(v));
    return t;
}

static __device__ __forceinline__ void mma_tf32(
    float* c, const uint32_t* a, uint32_t b0, uint32_t b1)
{
    asm volatile(
        "mma.sync.aligned.m16n8k8.row.col.f32.tf32.tf32.f32 "
        "{%0,%1,%2,%3}, {%4,%5,%6,%7}, {%8,%9}, {%0,%1,%2,%3};"
        : "+f"(c[0]), "+f"(c[1]), "+f"(c[2]), "+f"(c[3])
        : "r"(a[0]), "r"(a[1]), "r"(a[2]), "r"(a[3]), "r"(b0), "r"(b1));
}

static __device__ __forceinline__ void cp_async16(uint32_t dst_smem, const void* src) {
    asm volatile("cp.async.ca.shared.global [%0], [%1], 16;"
                 :: "r"(dst_smem), "l"(src) : "memory");
}
static __device__ __forceinline__ void cp_commit() {
    asm volatile("cp.async.commit_group;" ::: "memory");
}
template <int N>
static __device__ __forceinline__ void cp_wait() {
    asm volatile("cp.async.wait_group %0;" :: "n"(N) : "memory");
}
static __device__ __forceinline__ uint32_t smem_u32(const void* p) {
    uint32_t a;
    asm("{ .reg .u64 t; cvta.to.shared.u64 t, %1; cvt.u32.u64 %0, t; }"
        : "=r"(a) : "l"(p));
    return a;
}

// ---------------- kernel 0: pack W + zero sums ----------------
__global__ __launch_bounds__(256)
void pack_kernel(const float* __restrict__ W)
{
    int idx = blockIdx.x * 256 + threadIdx.x;        // 73728 total
    if (idx < BATCH * NGRP) { g_sum[idx] = 0.f; g_sumsq[idx] = 0.f; }
    if (idx >= 72 * 8 * 32 * 4) return;
    int j      = idx & 3;
    int lane   = (idx >> 2) & 31;
    int mt     = (idx >> 7) & 7;
    int kchunk = idx >> 10;
    int cg  = kchunk / 18;
    int t2  = kchunk % 18;
    int tap = t2 >> 1;
    int ci8 = t2 & 1;
    int kk = (lane & 3) + ((j >= 2) ? 4 : 0);
    int r  = (lane >> 2) + ((j & 1) ? 8 : 0);
    int cout = mt * 16 + r;
    int ci   = cg * 16 + ci8 * 8 + kk;
    int kh = tap / 3, kw = tap % 3;
    float v = W[((cout * CIN + ci) * 3 + kh) * 3 + kw];
    ((uint32_t*)g_wA)[idx] = f2tf32(v);
}

// ---------------- kernel 1: conv + bias + GN partials + fused 2x2 max/min ----
// Grid: (63, 32). CTA: 512 threads, 16 warps = 2M x 8N.
// Warp tile: 64 couts x 16 cols x 2 rows. nt: row = nt>>1, colblk = nt&1.
__global__ __launch_bounds__(512, 1)
void conv_mma_kernel(const float* __restrict__ x,
                     const float* __restrict__ bias)
{
    extern __shared__ uint32_t xs[];   // [2][XS_ELEMS] raw f32 bits (tf32 via truncation)
    const uint32_t xs_base = smem_u32(xs);

    const int tid  = threadIdx.x;
    const int wid  = tid >> 5;
    const int lane = tid & 31;
    const int warp_m = wid >> 3;            // 0..1
    const int warp_n = wid & 7;             // 0..7
    const int rg = blockIdx.x;              // pooled row
    const int b  = blockIdx.y;
    const int ho0 = rg * 2;

    // zero pad cols 128..135: 2buf x 16ci x 4row x 2q = 256 float4 slots
    if (tid < 256) {
        int qq  = tid & 1;
        int rr  = (tid >> 1) & 3;
        int cci = (tid >> 3) & 15;
        int bbf = tid >> 7;
        *reinterpret_cast<float4*>(xs + bbf * XS_ELEMS + cci * CI_STRIDE +
                                   rr * 136 + 128 + qq * 4) =
            make_float4(0.f, 0.f, 0.f, 0.f);
    }
    __syncthreads();

    // stage: 16 ci x 4 rows x 32 float4 = 2048 float4, 4 per thread
    auto stage = [&](int cg) {
        const uint32_t dstb = xs_base + (cg & 1) * (XS_ELEMS * 4);
        const float* src_base = x + (((size_t)b * CIN + cg * 16) * HIN + ho0) * WIN;
#pragma unroll
        for (int k = 0; k < 4; k++) {
            int c = tid + 512 * k;          // 0..2047
            int ci  = c >> 7;
            int rem = c & 127;
            int rr  = rem >> 5;
            int q   = rem & 31;
            cp_async16(dstb + (uint32_t)(ci * CI_STRIDE + rr * 136 + q * 4) * 4,
                       src_base + (size_t)ci * (HIN * WIN) + rr * WIN + q * 4);
        }
        cp_commit();
    };

    float acc[4][4][4];
#pragma unroll
    for (int i = 0; i < 4; i++)
#pragma unroll
        for (int n = 0; n < 4; n++)
#pragma unroll
            for (int k = 0; k < 4; k++) acc[i][n][k] = 0.f;

    const int lq = lane & 3;    // k index / col pair
    const int lr = lane >> 2;   // m row / col offset

    stage(0);

    for (int cg = 0; cg < 4; cg++) {
        if (cg + 1 < 4) stage(cg + 1);
        if (cg + 1 < 4) cp_wait<1>(); else cp_wait<0>();
        __syncthreads();

        const uint32_t* xbuf = xs + (cg & 1) * XS_ELEMS;

#pragma unroll
        for (int tap = 0; tap < 9; tap++) {
            const int kh = tap / 3, kw = tap % 3;
#pragma unroll
            for (int ci8 = 0; ci8 < 2; ci8++) {
                const int kchunk = cg * 18 + tap * 2 + ci8;
                uint32_t a[4][4];
#pragma unroll
                for (int i = 0; i < 4; i++) {
                    float4 f = __ldg(&reinterpret_cast<const float4*>(g_wA)[
                        (kchunk * 8 + warp_m * 4 + i) * 32 + lane]);
                    a[i][0] = __float_as_uint(f.x);
                    a[i][1] = __float_as_uint(f.y);
                    a[i][2] = __float_as_uint(f.z);
                    a[i][3] = __float_as_uint(f.w);
                }
                uint32_t b0[4], b1[4];
                const int cb = warp_n * 16 + lr + kw;
                const uint32_t* r0 = xbuf + (ci8 * 8 + lq)     * CI_STRIDE + kh * 136;
                const uint32_t* r1 = xbuf + (ci8 * 8 + lq + 4) * CI_STRIDE + kh * 136;
#pragma unroll
                for (int nt = 0; nt < 4; nt++) {
                    const int addr = (nt >> 1) * 136 + cb + (nt & 1) * 8;
                    b0[nt] = r0[addr];
                    b1[nt] = r1[addr];
                }
#pragma unroll
                for (int i = 0; i < 4; i++)
#pragma unroll
                    for (int nt = 0; nt < 4; nt++)
                        mma_tf32(acc[i][nt], a[i], b0[nt], b1[nt]);
            }
        }
        __syncthreads();
    }

    // ---- epilogue: bias, GN partials, fused 2x2 max/min, store pooled ----
    float sacc[4], qacc[4];
#pragma unroll
    for (int i = 0; i < 4; i++) { sacc[i] = 0.f; qacc[i] = 0.f; }

#pragma unroll
    for (int i = 0; i < 4; i++) {
        const int c0 = warp_m * 64 + i * 16 + lr;
        const int c1 = c0 + 8;
        const float bv0 = bias[c0];
        const float bv1 = bias[c1];
        float* pmax0 = g_pmax + (((size_t)b * COUT + c0) * HP + rg) * WP;
        float* pmin0 = g_pmin + (((size_t)b * COUT + c0) * HP + rg) * WP;
        float* pmax1 = g_pmax + (((size_t)b * COUT + c1) * HP + rg) * WP;
        float* pmin1 = g_pmin + (((size_t)b * COUT + c1) * HP + rg) * WP;
#pragma unroll
        for (int cblk = 0; cblk < 2; cblk++) {
            const int col = warp_n * 16 + cblk * 8 + 2 * lq;
            if (col < WO) {
                const int ntT = cblk;       // row0
                const int ntB = cblk + 2;   // row1
                float a00 = acc[i][ntT][0] + bv0, a01 = acc[i][ntT][1] + bv0;
                float a10 = acc[i][ntB][0] + bv0, a11 = acc[i][ntB][1] + bv0;
                float d00 = acc[i][ntT][2] + bv1, d01 = acc[i][ntT][3] + bv1;
                float d10 = acc[i][ntB][2] + bv1, d11 = acc[i][ntB][3] + bv1;

                sacc[i] += (a00 + a01 + a10 + a11) + (d00 + d01 + d10 + d11);
                qacc[i] += a00*a00 + a01*a01 + a10*a10 + a11*a11
                         + d00*d00 + d01*d01 + d10*d10 + d11*d11;

                const int wp = (col >> 1);
                pmax0[wp] = fmaxf(fmaxf(a00, a01), fmaxf(a10, a11));
                pmin0[wp] = fminf(fminf(a00, a01), fminf(a10, a11));
                pmax1[wp] = fmaxf(fmaxf(d00, d01), fmaxf(d10, d11));
                pmin1[wp] = fminf(fminf(d00, d01), fminf(d10, d11));
            }
        }
    }
#pragma unroll
    for (int i = 0; i < 4; i++) {
        float s = sacc[i], q = qacc[i];
#pragma unroll
        for (int off = 16; off > 0; off >>= 1) {
            s += __shfl_xor_sync(0xFFFFFFFF, s, off);
            q += __shfl_xor_sync(0xFFFFFFFF, q, off);
        }
        if (lane == 0) {
            const int g = warp_m * 4 + i;
            atomicAdd(&g_sum[b * NGRP + g], s);
            atomicAdd(&g_sumsq[b * NGRP + g], q);
        }
    }
}

// ---------------- kernel 2: finalize stats ----------------
__global__ void stats_final_kernel()
{
    int t = threadIdx.x;
    if (t < BATCH * NGRP) {
        const float n = (float)((COUT / NGRP) * HO * WO);
        float m = g_sum[t] / n;
        float var = g_sumsq[t] / n - m * m;
        g_mean[t] = m;
        g_rstd[t] = rsqrtf(var + EPS);
    }
}

// ---------------- kernel 3: elementwise normalize+clamp, 4-way unrolled ------
__global__ __launch_bounds__(256)
void final_kernel(const float* __restrict__ scale,
                  const float* __restrict__ gamma,
                  const float* __restrict__ beta,
                  float* __restrict__ out,
                  int total)
{
    const int stride = gridDim.x * 256;
    int idx = blockIdx.x * 256 + threadIdx.x;
#pragma unroll
    for (int u = 0; u < 4; u++, idx += stride) {
        if (idx < total) {
            int t = idx / (HP * WP);
            int c = t % COUT;
            int b = t / COUT;
            int g = c / (COUT / NGRP);

            const float mean = g_mean[b * NGRP + g];
            const float rstd = g_rstd[b * NGRP + g];
            const float a  = rstd * gamma[c] * scale[c];
            const float bb = (beta[c] - mean * rstd * gamma[c]) * scale[c];

            float v = (a >= 0.f) ? __ldcs(&g_pmax[idx]) : __ldcs(&g_pmin[idx]);
            float m = a * v + bb;
            out[idx] = fminf(fmaxf(m, 0.0f), 1.0f);
        }
    }
}

// ---------------- host launcher ----------------
extern "C" void kernel_launch(void* const* d_in, const int* in_sizes, int n_in,
                              void* d_out, int out_size)
{
    const float* x     = (const float*)d_in[0];
    const float* W     = (const float*)d_in[1];
    const float* bias  = (const float*)d_in[2];
    const float* scale = (const float*)d_in[3];
    const float* gamma = (const float*)d_in[4];
    const float* beta  = (const float*)d_in[5];
    float* out = (float*)d_out;

    static int smem_set = 0;
    const int smem_bytes = 2 * XS_ELEMS * 4;   // 70656
    if (!smem_set) {
        cudaFuncSetAttribute(conv_mma_kernel,
                             cudaFuncAttributeMaxDynamicSharedMemorySize, smem_bytes);
        smem_set = 1;
    }

    pack_kernel<<<288, 256>>>(W);

    dim3 cgrid(HP, BATCH);       // 63 x 32
    conv_mma_kernel<<<cgrid, 512, smem_bytes>>>(x, bias);

    stats_final_kernel<<<1, 256>>>();

    const int total = BATCH * COUT * HP * WP;
    final_kernel<<<(total / 4 + 255) / 256, 256>>>(scale, gamma, beta, out, total);
}

// round 8
// speedup vs baseline: 1.5487x; 1.5487x over previous
#include <cuda_runtime.h>
#include <cuda_fp16.h>
#include <cstdint>

// ---------------- problem shape ----------------
#define BATCH 32
#define CIN   64
#define HIN   128
#define WIN   128
#define COUT  128
#define HO    126
#define WO    126
#define NGRP  8
#define HP    63
#define WP    63
#define EPS   1e-5f

#define PSTRIDE 296               // words per ci-pair: 4 rows * 72 + 8 pad (≡8 mod 32)
#define XSW (8 * PSTRIDE)         // 2368 words = 9472 B

// ---------------- scratch (static device globals) ----------------
__device__ float    g_pmax[(size_t)BATCH * COUT * HP * WP];
__device__ float    g_pmin[(size_t)BATCH * COUT * HP * WP];
__device__ uint32_t g_wA16[36 * 8 * 32 * 4];   // W fragments, f16x2 words
__device__ float    g_sum[BATCH * NGRP];
__device__ float    g_sumsq[BATCH * NGRP];
__device__ float    g_mean[BATCH * NGRP];
__device__ float    g_rstd[BATCH * NGRP];

static __device__ __forceinline__ void mma_f16(
    float* c, const uint32_t* a, uint32_t b0, uint32_t b1)
{
    asm volatile(
        "mma.sync.aligned.m16n8k16.row.col.f32.f16.f16.f32 "
        "{%0,%1,%2,%3}, {%4,%5,%6,%7}, {%8,%9}, {%0,%1,%2,%3};"
        : "+f"(c[0]), "+f"(c[1]), "+f"(c[2]), "+f"(c[3])
        : "r"(a[0]), "r"(a[1]), "r"(a[2]), "r"(a[3]), "r"(b0), "r"(b1));
}

// ---------------- kernel 0: pack W into m16n8k16 fragment layout -------------
// g_wA16[((kchunk*8 + mt)*32 + lane)*4 + j], kchunk = cg*9 + tap (36 total)
// lane: lr=lane>>2, lq=lane&3.  j bit0: row +8; j bit1: k +8.
// frag elem: rows r=lr(+8), k = 2*lq(+8) paired with k+1 (f16x2: low = k even).
// cout = mt*16 + r, ci = cg*16 + k.
__global__ __launch_bounds__(256)
void pack_kernel(const float* __restrict__ W)
{
    int idx = blockIdx.x * 256 + threadIdx.x;      // 36864 total
    if (idx < BATCH * NGRP) { g_sum[idx] = 0.f; g_sumsq[idx] = 0.f; }
    if (idx >= 36 * 8 * 32 * 4) return;
    int j      = idx & 3;
    int lane   = (idx >> 2) & 31;
    int mt     = (idx >> 7) & 7;
    int kchunk = idx >> 10;                        // 0..35
    int cg  = kchunk / 9;
    int tap = kchunk % 9;
    int kh = tap / 3, kw = tap % 3;
    int lr = lane >> 2, lq = lane & 3;
    int r  = lr + (j & 1) * 8;
    int kb = 2 * lq + ((j >> 1) & 1) * 8;
    int cout = mt * 16 + r;
    int ci   = cg * 16 + kb;
    float w0 = W[((cout * CIN + ci)     * 3 + kh) * 3 + kw];
    float w1 = W[((cout * CIN + ci + 1) * 3 + kh) * 3 + kw];
    __half2 h = __floats2half2_rn(w0, w1);         // low = w0 (k even)
    g_wA16[idx] = *reinterpret_cast<uint32_t*>(&h);
}

// ---------------- kernel 1: fp16 implicit-GEMM conv + bias + GN partials -----
// ---------------- + fused 2x2 max/min pool -----------------------------------
// Grid: (126, 32): blockIdx.x = rg*2 + half. CTA: 128 couts x 2 rows x 64 cols.
// 8 warps = 2M x 4N; warp: 64 couts x 2 rows x 16 cols; nt: row=nt>>1, cblk=nt&1.
__global__ __launch_bounds__(256, 2)
void conv_mma_kernel(const float* __restrict__ x,
                     const float* __restrict__ bias)
{
    __shared__ uint32_t xs[XSW];    // f16x2 words: [ci_pair 8][row 4][col 72]

    const int tid  = threadIdx.x;
    const int wid  = tid >> 5;
    const int lane = tid & 31;
    const int warp_m = wid >> 2;            // 0..1
    const int warp_n = wid & 3;             // 0..3
    const int bx = blockIdx.x;
    const int rg   = bx >> 1;               // pooled row 0..62
    const int half = bx & 1;                // col half
    const int b  = blockIdx.y;
    const int ho0 = rg * 2;
    const int chb = half * 64;

    // zero pad words 68..71 for each (pair,row): 32 uint4 slots (done once)
    if (tid < 32) {
        int pair = tid >> 2, row = tid & 3;
        *reinterpret_cast<uint4*>(xs + pair * PSTRIDE + row * 72 + 68) =
            make_uint4(0, 0, 0, 0);
    }

    float acc[4][4][4];
#pragma unroll
    for (int i = 0; i < 4; i++)
#pragma unroll
        for (int n = 0; n < 4; n++)
#pragma unroll
            for (int k = 0; k < 4; k++) acc[i][n][k] = 0.f;

    const int lq = lane & 3;
    const int lr = lane >> 2;

    for (int cg = 0; cg < 4; cg++) {
        __syncthreads();    // previous compute done before overwriting buffer

        // ---- stage: 8 pairs x 4 rows x 17 quads = 544 tasks ----
#pragma unroll
        for (int t = 0; t < 3; t++) {
            int task = tid + 256 * t;
            if (task < 544) {
                int pair = task / 68;
                int rem  = task - pair * 68;
                int row  = rem / 17;
                int q    = rem - row * 17;
                int col  = chb + q * 4;
                float4 a0 = make_float4(0.f, 0.f, 0.f, 0.f);
                float4 a1 = a0;
                if (col <= 124) {
                    const float* p = x + (((size_t)b * CIN + cg * 16 + pair * 2)
                                          * HIN + (ho0 + row)) * WIN + col;
                    a0 = *reinterpret_cast<const float4*>(p);
                    a1 = *reinterpret_cast<const float4*>(p + HIN * WIN);
                }
                __half2 h0 = __floats2half2_rn(a0.x, a1.x);
                __half2 h1 = __floats2half2_rn(a0.y, a1.y);
                __half2 h2 = __floats2half2_rn(a0.z, a1.z);
                __half2 h3 = __floats2half2_rn(a0.w, a1.w);
                uint4 v;
                v.x = *reinterpret_cast<uint32_t*>(&h0);
                v.y = *reinterpret_cast<uint32_t*>(&h1);
                v.z = *reinterpret_cast<uint32_t*>(&h2);
                v.w = *reinterpret_cast<uint32_t*>(&h3);
                *reinterpret_cast<uint4*>(xs + pair * PSTRIDE + row * 72 + q * 4) = v;
            }
        }
        __syncthreads();

        // ---- compute 9 taps, K=16 each ----
#pragma unroll
        for (int tap = 0; tap < 9; tap++) {
            const int kh = tap / 3, kw = tap % 3;
            const int kchunk = cg * 9 + tap;
            uint32_t a[4][4];
#pragma unroll
            for (int i = 0; i < 4; i++) {
                uint4 f = __ldg(&reinterpret_cast<const uint4*>(g_wA16)[
                    (kchunk * 8 + warp_m * 4 + i) * 32 + lane]);
                a[i][0] = f.x; a[i][1] = f.y; a[i][2] = f.z; a[i][3] = f.w;
            }
            uint32_t b0[4], b1[4];
            const int cb = warp_n * 16 + lr + kw;
            const uint32_t* r0 = xs + lq * PSTRIDE + kh * 72;
            const uint32_t* r1 = xs + (lq + 4) * PSTRIDE + kh * 72;
#pragma unroll
            for (int nt = 0; nt < 4; nt++) {
                const int addr = (nt >> 1) * 72 + cb + (nt & 1) * 8;
                b0[nt] = r0[addr];
                b1[nt] = r1[addr];
            }
#pragma unroll
            for (int i = 0; i < 4; i++)
#pragma unroll
                for (int nt = 0; nt < 4; nt++)
                    mma_f16(acc[i][nt], a[i], b0[nt], b1[nt]);
        }
    }

    // ---- epilogue: bias, GN partials, fused 2x2 max/min, store pooled ----
    float sacc[4], qacc[4];
#pragma unroll
    for (int i = 0; i < 4; i++) { sacc[i] = 0.f; qacc[i] = 0.f; }

#pragma unroll
    for (int i = 0; i < 4; i++) {
        const int c0 = warp_m * 64 + i * 16 + lr;
        const int c1 = c0 + 8;
        const float bv0 = bias[c0];
        const float bv1 = bias[c1];
        float* pmax0 = g_pmax + (((size_t)b * COUT + c0) * HP + rg) * WP;
        float* pmin0 = g_pmin + (((size_t)b * COUT + c0) * HP + rg) * WP;
        float* pmax1 = g_pmax + (((size_t)b * COUT + c1) * HP + rg) * WP;
        float* pmin1 = g_pmin + (((size_t)b * COUT + c1) * HP + rg) * WP;
#pragma unroll
        for (int cblk = 0; cblk < 2; cblk++) {
            const int col = chb + warp_n * 16 + cblk * 8 + 2 * lq;
            if (col < WO) {
                const int ntT = cblk;       // row0
                const int ntB = cblk + 2;   // row1
                float a00 = acc[i][ntT][0] + bv0, a01 = acc[i][ntT][1] + bv0;
                float a10 = acc[i][ntB][0] + bv0, a11 = acc[i][ntB][1] + bv0;
                float d00 = acc[i][ntT][2] + bv1, d01 = acc[i][ntT][3] + bv1;
                float d10 = acc[i][ntB][2] + bv1, d11 = acc[i][ntB][3] + bv1;

                sacc[i] += (a00 + a01 + a10 + a11) + (d00 + d01 + d10 + d11);
                qacc[i] += a00*a00 + a01*a01 + a10*a10 + a11*a11
                         + d00*d00 + d01*d01 + d10*d10 + d11*d11;

                const int wp = (col >> 1);
                pmax0[wp] = fmaxf(fmaxf(a00, a01), fmaxf(a10, a11));
                pmin0[wp] = fminf(fminf(a00, a01), fminf(a10, a11));
                pmax1[wp] = fmaxf(fmaxf(d00, d01), fmaxf(d10, d11));
                pmin1[wp] = fminf(fminf(d00, d01), fminf(d10, d11));
            }
        }
    }
#pragma unroll
    for (int i = 0; i < 4; i++) {
        float s = sacc[i], q = qacc[i];
#pragma unroll
        for (int off = 16; off > 0; off >>= 1) {
            s += __shfl_xor_sync(0xFFFFFFFF, s, off);
            q += __shfl_xor_sync(0xFFFFFFFF, q, off);
        }
        if (lane == 0) {
            const int g = warp_m * 4 + i;
            atomicAdd(&g_sum[b * NGRP + g], s);
            atomicAdd(&g_sumsq[b * NGRP + g], q);
        }
    }
}

// ---------------- kernel 2: finalize stats ----------------
__global__ void stats_final_kernel()
{
    int t = threadIdx.x;
    if (t < BATCH * NGRP) {
        const float n = (float)((COUT / NGRP) * HO * WO);
        float m = g_sum[t] / n;
        float var = g_sumsq[t] / n - m * m;
        g_mean[t] = m;
        g_rstd[t] = rsqrtf(var + EPS);
    }
}

// ---------------- kernel 3: normalize + clamp on pooled max/min --------------
// Grid: (16, BATCH*COUT); no per-element integer divisions.
__global__ __launch_bounds__(256)
void final_kernel(const float* __restrict__ scale,
                  const float* __restrict__ gamma,
                  const float* __restrict__ beta,
                  float* __restrict__ out)
{
    int pix = blockIdx.x * 256 + threadIdx.x;
    if (pix >= HP * WP) return;
    int t = blockIdx.y;
    int c = t & (COUT - 1);
    int b = t >> 7;
    int g = c >> 4;

    const float mean = g_mean[b * NGRP + g];
    const float rstd = g_rstd[b * NGRP + g];
    const float a  = rstd * gamma[c] * scale[c];
    const float bb = (beta[c] - mean * rstd * gamma[c]) * scale[c];

    size_t idx = (size_t)t * (HP * WP) + pix;
    float v = (a >= 0.f) ? __ldcs(&g_pmax[idx]) : __ldcs(&g_pmin[idx]);
    float m = a * v + bb;
    out[idx] = fminf(fmaxf(m, 0.0f), 1.0f);
}

// ---------------- host launcher ----------------
extern "C" void kernel_launch(void* const* d_in, const int* in_sizes, int n_in,
                              void* d_out, int out_size)
{
    const float* x     = (const float*)d_in[0];
    const float* W     = (const float*)d_in[1];
    const float* bias  = (const float*)d_in[2];
    const float* scale = (const float*)d_in[3];
    const float* gamma = (const float*)d_in[4];
    const float* beta  = (const float*)d_in[5];
    float* out = (float*)d_out;

    pack_kernel<<<144, 256>>>(W);

    dim3 cgrid(2 * HP, BATCH);       // 126 x 32
    conv_mma_kernel<<<cgrid, 256>>>(x, bias);

    stats_final_kernel<<<1, 256>>>();

    dim3 fgrid((HP * WP + 255) / 256, BATCH * COUT);   // 16 x 4096
    final_kernel<<<fgrid, 256>>>(scale, gamma, beta, out);
}

// round 10
// speedup vs baseline: 1.6880x; 1.0900x over previous
#include <cuda_runtime.h>
#include <cuda_fp16.h>
#include <cstdint>

// ---------------- problem shape ----------------
#define BATCH 32
#define CIN   64
#define HIN   128
#define WIN   128
#define COUT  128
#define HO    126
#define WO    126
#define NGRP  8
#define HP    63
#define WP    63
#define EPS   1e-5f

#define PSTRIDE 296               // f16x2 words per ci-pair: 4 rows * 72 + 8 pad (≡8 mod 32)
#define XSW (8 * PSTRIDE)         // 2368 words = 9472 B
#define RSTRIDE 276               // raw f32 words per ci: 4 rows * 68 + 4 pad
#define RAWW (16 * RSTRIDE)       // 4416 words per buffer

// ---------------- scratch (static device globals) ----------------
__device__ float    g_pmax[(size_t)BATCH * COUT * HP * WP];
__device__ float    g_pmin[(size_t)BATCH * COUT * HP * WP];
__device__ uint32_t g_wA16[36 * 8 * 32 * 4];   // W fragments, f16x2 words
__device__ float    g_sum[BATCH * NGRP];
__device__ float    g_sumsq[BATCH * NGRP];
__device__ float    g_mean[BATCH * NGRP];
__device__ float    g_rstd[BATCH * NGRP];

static __device__ __forceinline__ void mma_f16(
    float* c, const uint32_t* a, uint32_t b0, uint32_t b1)
{
    asm volatile(
        "mma.sync.aligned.m16n8k16.row.col.f32.f16.f16.f32 "
        "{%0,%1,%2,%3}, {%4,%5,%6,%7}, {%8,%9}, {%0,%1,%2,%3};"
        : "+f"(c[0]), "+f"(c[1]), "+f"(c[2]), "+f"(c[3])
        : "r"(a[0]), "r"(a[1]), "r"(a[2]), "r"(a[3]), "r"(b0), "r"(b1));
}

static __device__ __forceinline__ void cp_async16(uint32_t dst_smem, const void* src) {
    asm volatile("cp.async.ca.shared.global [%0], [%1], 16;"
                 :: "r"(dst_smem), "l"(src) : "memory");
}
static __device__ __forceinline__ void cp_commit() {
    asm volatile("cp.async.commit_group;" ::: "memory");
}
template <int N>
static __device__ __forceinline__ void cp_wait() {
    asm volatile("cp.async.wait_group %0;" :: "n"(N) : "memory");
}
static __device__ __forceinline__ uint32_t smem_u32(const void* p) {
    uint32_t a;
    asm("{ .reg .u64 t; cvta.to.shared.u64 t, %1; cvt.u32.u64 %0, t; }"
        : "=r"(a) : "l"(p));
    return a;
}

// ---------------- kernel 0: pack W into m16n8k16 fragment layout -------------
__global__ __launch_bounds__(256)
void pack_kernel(const float* __restrict__ W)
{
    int idx = blockIdx.x * 256 + threadIdx.x;      // 36864 total
    if (idx < BATCH * NGRP) { g_sum[idx] = 0.f; g_sumsq[idx] = 0.f; }
    if (idx >= 36 * 8 * 32 * 4) return;
    int j      = idx & 3;
    int lane   = (idx >> 2) & 31;
    int mt     = (idx >> 7) & 7;
    int kchunk = idx >> 10;                        // 0..35
    int cg  = kchunk / 9;
    int tap = kchunk % 9;
    int kh = tap / 3, kw = tap % 3;
    int lr = lane >> 2, lq = lane & 3;
    int r  = lr + (j & 1) * 8;
    int kb = 2 * lq + ((j >> 1) & 1) * 8;
    int cout = mt * 16 + r;
    int ci   = cg * 16 + kb;
    float w0 = W[((cout * CIN + ci)     * 3 + kh) * 3 + kw];
    float w1 = W[((cout * CIN + ci + 1) * 3 + kh) * 3 + kw];
    __half2 h = __floats2half2_rn(w0, w1);         // low = w0 (k even)
    g_wA16[idx] = *reinterpret_cast<uint32_t*>(&h);
}

// ---------------- kernel 1: fp16 implicit-GEMM conv, cp.async pipelined ------
// Grid: (126, 32): blockIdx.x = rg*2 + half. CTA: 128 couts x 2 rows x 64 cols.
// 8 warps = 2M x 4N; warp: 64 couts x 2 rows x 16 cols; nt: row=nt>>1, cblk=nt&1.
__global__ __launch_bounds__(256, 2)
void conv_mma_kernel(const float* __restrict__ x,
                     const float* __restrict__ bias)
{
    __shared__ uint32_t xs[XSW];          // f16x2: [pair 8][row 4][72]
    __shared__ uint32_t raw[2][RAWW];     // raw f32 bits: [ci 16][row 4][68]+pad
    const uint32_t raw_base = smem_u32(raw);

    const int tid  = threadIdx.x;
    const int wid  = tid >> 5;
    const int lane = tid & 31;
    const int warp_m = wid >> 2;            // 0..1
    const int warp_n = wid & 3;             // 0..3
    const int bx = blockIdx.x;
    const int rg   = bx >> 1;               // pooled row 0..62
    const int half = bx & 1;                // col half
    const int b  = blockIdx.y;
    const int ho0 = rg * 2;
    const int chb = half * 64;

    // zero pad words 68..71 of each (pair,row) in f16 buffer (once)
    if (tid < 32) {
        int pair = tid >> 2, row = tid & 3;
        *reinterpret_cast<uint4*>(xs + pair * PSTRIDE + row * 72 + 68) =
            make_uint4(0, 0, 0, 0);
    }

    // cp.async stage of raw f32 chunk cg -> raw[(cg)&1]
    auto stage = [&](int cg) {
        const uint32_t dstb = raw_base + (uint32_t)(cg & 1) * (RAWW * 4);
        const float* src_base = x + (((size_t)b * CIN + cg * 16) * HIN + ho0) * WIN;
#pragma unroll
        for (int t = 0; t < 5; t++) {
            int task = tid + 256 * t;           // 0..1087
            if (task < 1088) {
                int ci  = task / 68;
                int rem = task - ci * 68;
                int row = rem / 17;
                int q   = rem - row * 17;
                int col = chb + q * 4;
                if (col <= 124)
                    cp_async16(dstb + (uint32_t)(ci * RSTRIDE + row * 68 + q * 4) * 4,
                               src_base + (size_t)ci * (HIN * WIN) + row * WIN + col);
            }
        }
        cp_commit();
    };

    // convert raw[(cg)&1] -> f16 buffer xs
    auto convert = [&](int cg) {
        const uint32_t* rb = raw[cg & 1];
#pragma unroll
        for (int t = 0; t < 3; t++) {
            int task = tid + 256 * t;           // 0..543
            if (task < 544) {
                int pair = task / 68;
                int rem  = task - pair * 68;
                int row  = rem / 17;
                int q    = rem - row * 17;
                int col  = chb + q * 4;
                float4 a0 = make_float4(0.f, 0.f, 0.f, 0.f);
                float4 a1 = a0;
                if (col <= 124) {
                    a0 = *reinterpret_cast<const float4*>(
                        rb + (2 * pair)     * RSTRIDE + row * 68 + q * 4);
                    a1 = *reinterpret_cast<const float4*>(
                        rb + (2 * pair + 1) * RSTRIDE + row * 68 + q * 4);
                }
                __half2 h0 = __floats2half2_rn(a0.x, a1.x);
                __half2 h1 = __floats2half2_rn(a0.y, a1.y);
                __half2 h2 = __floats2half2_rn(a0.z, a1.z);
                __half2 h3 = __floats2half2_rn(a0.w, a1.w);
                uint4 v;
                v.x = *reinterpret_cast<uint32_t*>(&h0);
                v.y = *reinterpret_cast<uint32_t*>(&h1);
                v.z = *reinterpret_cast<uint32_t*>(&h2);
                v.w = *reinterpret_cast<uint32_t*>(&h3);
                *reinterpret_cast<uint4*>(xs + pair * PSTRIDE + row * 72 + q * 4) = v;
            }
        }
    };

    float acc[4][4][4];
#pragma unroll
    for (int i = 0; i < 4; i++)
#pragma unroll
        for (int n = 0; n < 4; n++)
#pragma unroll
            for (int k = 0; k < 4; k++) acc[i][n][k] = 0.f;

    const int lq = lane & 3;
    const int lr = lane >> 2;

    stage(0);

    for (int cg = 0; cg < 4; cg++) {
        cp_wait<0>();
        __syncthreads();        // raw ready; previous MMA done (xs reusable)
        convert(cg);
        __syncthreads();        // f16 tile ready
        if (cg + 1 < 4) stage(cg + 1);   // DMA overlaps MMA below

#pragma unroll
        for (int tap = 0; tap < 9; tap++) {
            const int kh = tap / 3, kw = tap % 3;
            const int kchunk = cg * 9 + tap;
            uint32_t a[4][4];
#pragma unroll
            for (int i = 0; i < 4; i++) {
                uint4 f = __ldg(&reinterpret_cast<const uint4*>(g_wA16)[
                    (kchunk * 8 + warp_m * 4 + i) * 32 + lane]);
                a[i][0] = f.x; a[i][1] = f.y; a[i][2] = f.z; a[i][3] = f.w;
            }
            uint32_t b0[4], b1[4];
            const int cb = warp_n * 16 + lr + kw;
            const uint32_t* r0 = xs + lq * PSTRIDE + kh * 72;
            const uint32_t* r1 = xs + (lq + 4) * PSTRIDE + kh * 72;
#pragma unroll
            for (int nt = 0; nt < 4; nt++) {
                const int addr = (nt >> 1) * 72 + cb + (nt & 1) * 8;
                b0[nt] = r0[addr];
                b1[nt] = r1[addr];
            }
#pragma unroll
            for (int i = 0; i < 4; i++)
#pragma unroll
                for (int nt = 0; nt < 4; nt++)
                    mma_f16(acc[i][nt], a[i], b0[nt], b1[nt]);
        }
    }

    // ---- epilogue: bias, GN partials, fused 2x2 max/min, store pooled ----
    float sacc[4], qacc[4];
#pragma unroll
    for (int i = 0; i < 4; i++) { sacc[i] = 0.f; qacc[i] = 0.f; }

#pragma unroll
    for (int i = 0; i < 4; i++) {
        const int c0 = warp_m * 64 + i * 16 + lr;
        const int c1 = c0 + 8;
        const float bv0 = bias[c0];
        const float bv1 = bias[c1];
        float* pmax0 = g_pmax + (((size_t)b * COUT + c0) * HP + rg) * WP;
        float* pmin0 = g_pmin + (((size_t)b * COUT + c0) * HP + rg) * WP;
        float* pmax1 = g_pmax + (((size_t)b * COUT + c1) * HP + rg) * WP;
        float* pmin1 = g_pmin + (((size_t)b * COUT + c1) * HP + rg) * WP;
#pragma unroll
        for (int cblk = 0; cblk < 2; cblk++) {
            const int col = chb + warp_n * 16 + cblk * 8 + 2 * lq;
            if (col < WO) {
                const int ntT = cblk;       // row0
                const int ntB = cblk + 2;   // row1
                float a00 = acc[i][ntT][0] + bv0, a01 = acc[i][ntT][1] + bv0;
                float a10 = acc[i][ntB][0] + bv0, a11 = acc[i][ntB][1] + bv0;
                float d00 = acc[i][ntT][2] + bv1, d01 = acc[i][ntT][3] + bv1;
                float d10 = acc[i][ntB][2] + bv1, d11 = acc[i][ntB][3] + bv1;

                sacc[i] += (a00 + a01 + a10 + a11) + (d00 + d01 + d10 + d11);
                qacc[i] += a00*a00 + a01*a01 + a10*a10 + a11*a11
                         + d00*d00 + d01*d01 + d10*d10 + d11*d11;

                const int wp = (col >> 1);
                pmax0[wp] = fmaxf(fmaxf(a00, a01), fmaxf(a10, a11));
                pmin0[wp] = fminf(fminf(a00, a01), fminf(a10, a11));
                pmax1[wp] = fmaxf(fmaxf(d00, d01), fmaxf(d10, d11));
                pmin1[wp] = fminf(fminf(d00, d01), fminf(d10, d11));
            }
        }
    }
#pragma unroll
    for (int i = 0; i < 4; i++) {
        float s = sacc[i], q = qacc[i];
#pragma unroll
        for (int off = 16; off > 0; off >>= 1) {
            s += __shfl_xor_sync(0xFFFFFFFF, s, off);
            q += __shfl_xor_sync(0xFFFFFFFF, q, off);
        }
        if (lane == 0) {
            const int g = warp_m * 4 + i;
            atomicAdd(&g_sum[b * NGRP + g], s);
            atomicAdd(&g_sumsq[b * NGRP + g], q);
        }
    }
}

// ---------------- kernel 2: finalize stats ----------------
__global__ void stats_final_kernel()
{
    int t = threadIdx.x;
    if (t < BATCH * NGRP) {
        const float n = (float)((COUT / NGRP) * HO * WO);
        float m = g_sum[t] / n;
        float var = g_sumsq[t] / n - m * m;
        g_mean[t] = m;
        g_rstd[t] = rsqrtf(var + EPS);
    }
}

// ---------------- kernel 3: normalize + clamp, one block per (b,c) plane -----
// 256 threads x 16 pixels at stride 256 => covers 4096 >= 3969. Loads batched.
__global__ __launch_bounds__(256)
void final_kernel(const float* __restrict__ scale,
                  const float* __restrict__ gamma,
                  const float* __restrict__ beta,
                  float* __restrict__ out)
{
    const int t = blockIdx.x;              // b*COUT + c
    const int c = t & (COUT - 1);
    const int b = t >> 7;
    const int g = c >> 4;

    const float mean = g_mean[b * NGRP + g];
    const float rstd = g_rstd[b * NGRP + g];
    const float a  = rstd * gamma[c] * scale[c];
    const float bb = (beta[c] - mean * rstd * gamma[c]) * scale[c];

    const size_t base = (size_t)t * (HP * WP);
    const float* src = (a >= 0.f) ? (g_pmax + base) : (g_pmin + base);
    float* dst = out + base;

    float v[16];
#pragma unroll
    for (int u = 0; u < 16; u++) {
        int p = threadIdx.x + u * 256;
        v[u] = (p < HP * WP) ? __ldcs(&src[p]) : 0.f;
    }
#pragma unroll
    for (int u = 0; u < 16; u++) {
        int p = threadIdx.x + u * 256;
        if (p < HP * WP) {
            float m = a * v[u] + bb;
            dst[p] = fminf(fmaxf(m, 0.0f), 1.0f);
        }
    }
}

// ---------------- host launcher ----------------
extern "C" void kernel_launch(void* const* d_in, const int* in_sizes, int n_in,
                              void* d_out, int out_size)
{
    const float* x     = (const float*)d_in[0];
    const float* W     = (const float*)d_in[1];
    const float* bias  = (const float*)d_in[2];
    const float* scale = (const float*)d_in[3];
    const float* gamma = (const float*)d_in[4];
    const float* beta  = (const float*)d_in[5];
    float* out = (float*)d_out;

    pack_kernel<<<144, 256>>>(W);

    dim3 cgrid(2 * HP, BATCH);       // 126 x 32
    conv_mma_kernel<<<cgrid, 256>>>(x, bias);

    stats_final_kernel<<<1, 256>>>();

    final_kernel<<<BATCH * COUT, 256>>>(scale, gamma, beta, out);
}

// round 11
// speedup vs baseline: 1.7652x; 1.0457x over previous
#include <cuda_runtime.h>
#include <cuda_fp16.h>
#include <cstdint>

// ---------------- problem shape ----------------
#define BATCH 32
#define CIN   64
#define HIN   128
#define WIN   128
#define COUT  128
#define HO    126
#define WO    126
#define NGRP  8
#define HP    63
#define WP    63
#define EPS   1e-5f

#define PSTRIDE 296               // f16x2 words per ci-pair: 4 rows * 72 + 8 pad (≡8 mod 32)
#define XSW (8 * PSTRIDE)         // 2368 words = 9472 B

// ---------------- scratch (static device globals) ----------------
__device__ float    g_pmax[(size_t)BATCH * COUT * HP * WP];
__device__ float    g_pmin[(size_t)BATCH * COUT * HP * WP];
__device__ uint32_t g_wA16[36 * 8 * 32 * 4];   // W fragments, f16x2 words
__device__ float    g_sum[BATCH * NGRP];
__device__ float    g_sumsq[BATCH * NGRP];

// NOTE: non-volatile on purpose — lets ptxas software-pipeline loads across MMAs.
static __device__ __forceinline__ void mma_f16(
    float* c, const uint32_t* a, uint32_t b0, uint32_t b1)
{
    asm("mma.sync.aligned.m16n8k16.row.col.f32.f16.f16.f32 "
        "{%0,%1,%2,%3}, {%4,%5,%6,%7}, {%8,%9}, {%0,%1,%2,%3};"
        : "+f"(c[0]), "+f"(c[1]), "+f"(c[2]), "+f"(c[3])
        : "r"(a[0]), "r"(a[1]), "r"(a[2]), "r"(a[3]), "r"(b0), "r"(b1));
}

// ---------------- kernel 0: pack W into m16n8k16 fragment layout -------------
__global__ __launch_bounds__(256)
void pack_kernel(const float* __restrict__ W)
{
    int idx = blockIdx.x * 256 + threadIdx.x;      // 36864 total
    if (idx < BATCH * NGRP) { g_sum[idx] = 0.f; g_sumsq[idx] = 0.f; }
    if (idx >= 36 * 8 * 32 * 4) return;
    int j      = idx & 3;
    int lane   = (idx >> 2) & 31;
    int mt     = (idx >> 7) & 7;
    int kchunk = idx >> 10;                        // 0..35
    int cg  = kchunk / 9;
    int tap = kchunk % 9;
    int kh = tap / 3, kw = tap % 3;
    int lr = lane >> 2, lq = lane & 3;
    int r  = lr + (j & 1) * 8;
    int kb = 2 * lq + ((j >> 1) & 1) * 8;
    int cout = mt * 16 + r;
    int ci   = cg * 16 + kb;
    float w0 = W[((cout * CIN + ci)     * 3 + kh) * 3 + kw];
    float w1 = W[((cout * CIN + ci + 1) * 3 + kh) * 3 + kw];
    __half2 h = __floats2half2_rn(w0, w1);         // low = w0 (k even)
    g_wA16[idx] = *reinterpret_cast<uint32_t*>(&h);
}

// ---------------- kernel 1: fp16 implicit-GEMM conv + fused pool -------------
// Grid: (126, 32): blockIdx.x = rg*2 + half. CTA: 128 couts x 2 rows x 64 cols.
// 8 warps = 2M x 4N; warp: 64 couts x 2 rows x 16 cols; nt: row=nt>>1, cblk=nt&1.
__global__ __launch_bounds__(256, 2)
void conv_mma_kernel(const float* __restrict__ x,
                     const float* __restrict__ bias)
{
    __shared__ uint32_t xs[XSW];    // f16x2 words: [ci_pair 8][row 4][col 72]

    const int tid  = threadIdx.x;
    const int wid  = tid >> 5;
    const int lane = tid & 31;
    const int warp_m = wid >> 2;            // 0..1
    const int warp_n = wid & 3;             // 0..3
    const int bx = blockIdx.x;
    const int rg   = bx >> 1;               // pooled row 0..62
    const int half = bx & 1;                // col half
    const int b  = blockIdx.y;
    const int ho0 = rg * 2;
    const int chb = half * 64;

    // zero pad words 68..71 for each (pair,row): 32 uint4 slots (once)
    if (tid < 32) {
        int pair = tid >> 2, row = tid & 3;
        *reinterpret_cast<uint4*>(xs + pair * PSTRIDE + row * 72 + 68) =
            make_uint4(0, 0, 0, 0);
    }

    float acc[4][4][4];
#pragma unroll
    for (int i = 0; i < 4; i++)
#pragma unroll
        for (int n = 0; n < 4; n++)
#pragma unroll
            for (int k = 0; k < 4; k++) acc[i][n][k] = 0.f;

    const int lq = lane & 3;
    const int lr = lane >> 2;

    uint32_t a_cur[4][4], a_nxt[4][4];

    auto load_a = [&](int kchunk, uint32_t (&dst)[4][4]) {
#pragma unroll
        for (int i = 0; i < 4; i++) {
            uint4 f = __ldg(&reinterpret_cast<const uint4*>(g_wA16)[
                (kchunk * 8 + warp_m * 4 + i) * 32 + lane]);
            dst[i][0] = f.x; dst[i][1] = f.y; dst[i][2] = f.z; dst[i][3] = f.w;
        }
    };

    for (int cg = 0; cg < 4; cg++) {
        __syncthreads();    // previous compute done before overwriting buffer

        // ---- stage: 8 pairs x 4 rows x 17 quads = 544 tasks ----
#pragma unroll
        for (int t = 0; t < 3; t++) {
            int task = tid + 256 * t;
            if (task < 544) {
                int pair = task / 68;
                int rem  = task - pair * 68;
                int row  = rem / 17;
                int q    = rem - row * 17;
                int col  = chb + q * 4;
                float4 a0 = make_float4(0.f, 0.f, 0.f, 0.f);
                float4 a1 = a0;
                if (col <= 124) {
                    const float* p = x + (((size_t)b * CIN + cg * 16 + pair * 2)
                                          * HIN + (ho0 + row)) * WIN + col;
                    a0 = *reinterpret_cast<const float4*>(p);
                    a1 = *reinterpret_cast<const float4*>(p + HIN * WIN);
                }
                __half2 h0 = __floats2half2_rn(a0.x, a1.x);
                __half2 h1 = __floats2half2_rn(a0.y, a1.y);
                __half2 h2 = __floats2half2_rn(a0.z, a1.z);
                __half2 h3 = __floats2half2_rn(a0.w, a1.w);
                uint4 v;
                v.x = *reinterpret_cast<uint32_t*>(&h0);
                v.y = *reinterpret_cast<uint32_t*>(&h1);
                v.z = *reinterpret_cast<uint32_t*>(&h2);
                v.w = *reinterpret_cast<uint32_t*>(&h3);
                *reinterpret_cast<uint4*>(xs + pair * PSTRIDE + row * 72 + q * 4) = v;
            }
        }
        __syncthreads();

        // ---- compute 9 taps, K=16 each; A fragments double-buffered ----
        load_a(cg * 9, a_cur);
#pragma unroll
        for (int tap = 0; tap < 9; tap++) {
            if (tap < 8) load_a(cg * 9 + tap + 1, a_nxt);

            const int kh = tap / 3, kw = tap % 3;
            uint32_t b0[4], b1[4];
            const int cb = warp_n * 16 + lr + kw;
            const uint32_t* r0 = xs + lq * PSTRIDE + kh * 72;
            const uint32_t* r1 = xs + (lq + 4) * PSTRIDE + kh * 72;
#pragma unroll
            for (int nt = 0; nt < 4; nt++) {
                const int addr = (nt >> 1) * 72 + cb + (nt & 1) * 8;
                b0[nt] = r0[addr];
                b1[nt] = r1[addr];
            }
#pragma unroll
            for (int i = 0; i < 4; i++)
#pragma unroll
                for (int nt = 0; nt < 4; nt++)
                    mma_f16(acc[i][nt], a_cur[i], b0[nt], b1[nt]);

#pragma unroll
            for (int i = 0; i < 4; i++)
#pragma unroll
                for (int j = 0; j < 4; j++)
                    a_cur[i][j] = a_nxt[i][j];
        }
    }

    // ---- epilogue: bias, GN partials, fused 2x2 max/min, store pooled ----
    float sacc[4], qacc[4];
#pragma unroll
    for (int i = 0; i < 4; i++) { sacc[i] = 0.f; qacc[i] = 0.f; }

#pragma unroll
    for (int i = 0; i < 4; i++) {
        const int c0 = warp_m * 64 + i * 16 + lr;
        const int c1 = c0 + 8;
        const float bv0 = bias[c0];
        const float bv1 = bias[c1];
        float* pmax0 = g_pmax + (((size_t)b * COUT + c0) * HP + rg) * WP;
        float* pmin0 = g_pmin + (((size_t)b * COUT + c0) * HP + rg) * WP;
        float* pmax1 = g_pmax + (((size_t)b * COUT + c1) * HP + rg) * WP;
        float* pmin1 = g_pmin + (((size_t)b * COUT + c1) * HP + rg) * WP;
#pragma unroll
        for (int cblk = 0; cblk < 2; cblk++) {
            const int col = chb + warp_n * 16 + cblk * 8 + 2 * lq;
            if (col < WO) {
                const int ntT = cblk;       // row0
                const int ntB = cblk + 2;   // row1
                float a00 = acc[i][ntT][0] + bv0, a01 = acc[i][ntT][1] + bv0;
                float a10 = acc[i][ntB][0] + bv0, a11 = acc[i][ntB][1] + bv0;
                float d00 = acc[i][ntT][2] + bv1, d01 = acc[i][ntT][3] + bv1;
                float d10 = acc[i][ntB][2] + bv1, d11 = acc[i][ntB][3] + bv1;

                sacc[i] += (a00 + a01 + a10 + a11) + (d00 + d01 + d10 + d11);
                qacc[i] += a00*a00 + a01*a01 + a10*a10 + a11*a11
                         + d00*d00 + d01*d01 + d10*d10 + d11*d11;

                const int wp = (col >> 1);
                pmax0[wp] = fmaxf(fmaxf(a00, a01), fmaxf(a10, a11));
                pmin0[wp] = fminf(fminf(a00, a01), fminf(a10, a11));
                pmax1[wp] = fmaxf(fmaxf(d00, d01), fmaxf(d10, d11));
                pmin1[wp] = fminf(fminf(d00, d01), fminf(d10, d11));
            }
        }
    }
#pragma unroll
    for (int i = 0; i < 4; i++) {
        float s = sacc[i], q = qacc[i];
#pragma unroll
        for (int off = 16; off > 0; off >>= 1) {
            s += __shfl_xor_sync(0xFFFFFFFF, s, off);
            q += __shfl_xor_sync(0xFFFFFFFF, q, off);
        }
        if (lane == 0) {
            const int g = warp_m * 4 + i;
            atomicAdd(&g_sum[b * NGRP + g], s);
            atomicAdd(&g_sumsq[b * NGRP + g], q);
        }
    }
}

// ---------------- kernel 2: normalize + clamp (stats computed inline) --------
// One block per (b,c) plane; 256 threads x 16 pixels stride 256.
__global__ __launch_bounds__(256)
void final_kernel(const float* __restrict__ scale,
                  const float* __restrict__ gamma,
                  const float* __restrict__ beta,
                  float* __restrict__ out)
{
    const int t = blockIdx.x;              // b*COUT + c
    const int c = t & (COUT - 1);
    const int b = t >> 7;
    const int g = c >> 4;

    const float n = (float)((COUT / NGRP) * HO * WO);
    const float mean = g_sum[b * NGRP + g] / n;
    const float var  = g_sumsq[b * NGRP + g] / n - mean * mean;
    const float rstd = rsqrtf(var + EPS);
    const float a  = rstd * gamma[c] * scale[c];
    const float bb = (beta[c] - mean * rstd * gamma[c]) * scale[c];

    const size_t base = (size_t)t * (HP * WP);
    const float* src = (a >= 0.f) ? (g_pmax + base) : (g_pmin + base);
    float* dst = out + base;

    float v[16];
#pragma unroll
    for (int u = 0; u < 16; u++) {
        int p = threadIdx.x + u * 256;
        v[u] = (p < HP * WP) ? __ldcs(&src[p]) : 0.f;
    }
#pragma unroll
    for (int u = 0; u < 16; u++) {
        int p = threadIdx.x + u * 256;
        if (p < HP * WP) {
            float m = a * v[u] + bb;
            dst[p] = fminf(fmaxf(m, 0.0f), 1.0f);
        }
    }
}

// ---------------- host launcher ----------------
extern "C" void kernel_launch(void* const* d_in, const int* in_sizes, int n_in,
                              void* d_out, int out_size)
{
    const float* x     = (const float*)d_in[0];
    const float* W     = (const float*)d_in[1];
    const float* bias  = (const float*)d_in[2];
    const float* scale = (const float*)d_in[3];
    const float* gamma = (const float*)d_in[4];
    const float* beta  = (const float*)d_in[5];
    float* out = (float*)d_out;

    pack_kernel<<<144, 256>>>(W);

    dim3 cgrid(2 * HP, BATCH);       // 126 x 32
    conv_mma_kernel<<<cgrid, 256>>>(x, bias);

    final_kernel<<<BATCH * COUT, 256>>>(scale, gamma, beta, out);
}